// round 8
// baseline (speedup 1.0000x reference)
#include <cuda_runtime.h>
#include <cstdint>

#define NB 32
#define NT 400
#define ND 2048
#define S_DEN 2000
#define E_DEN 60000
#define S_NUM 512
#define E_NUM 2048
#define CS 8          // cluster size
#define NCL 16        // clusters
#define DPER 8        // den edges per thread (~7500/1024 -> 8)

// ---- dynamic smem layout (bytes) ----
#define OFF_AD    0        // float[2][S_DEN]        16000
#define OFF_CLD   16000    // float[S_DEN]            8000
#define OFF_XT    24000    // float[2][ND]           16384 (16B aligned)
#define OFF_AN    40384    // float[2][S_NUM]         4096
#define OFF_CLN   44480    // float[S_NUM]            2048
#define OFF_AW    46528    // float[S_DEN]            8000
#define OFF_AWN   54528    // float[S_NUM]            2048
#define OFF_NE    56576    // uint2[1024]             8192 (16B aligned)
#define OFF_ND    64768    // u16[1024]               2048
#define OFF_SRD   66816    // float[32]                128
#define OFF_SRN   66944    // float[32]                128
#define OFF_MAILD 67072    // float[2][8]               64
#define OFF_MAILN 67136    // float[2][8]               64
#define OFF_MBAR  67200    // u64[2] ping-pong          16
#define OFF_DPR   67232    // float[DPER*1024]       32768
#define OFF_DDS   100000   // u16[DPER*1024]         16384
#define SMEM_MAIN 116480

// ---------------- device scratch ----------------
__device__ int g_dfill[S_DEN];
__device__ int g_drow[S_DEN + 1];
__device__ uint2 g_dedge[E_DEN];
__device__ unsigned short g_dout[E_DEN];
__device__ int g_dscut[CS + 1];
__device__ int g_decut[CS + 1];

__device__ int g_nfill[NB * S_NUM];
__device__ int g_nrow[NB * (S_NUM + 1)];
__device__ uint2 g_nedge[NB * E_NUM];
__device__ unsigned short g_nout[NB * E_NUM];
__device__ int g_nscut[NB * (CS + 1)];
__device__ int g_necut[NB * (CS + 1)];

__device__ float g_objd[NB];
__device__ float g_objn[NB];

__device__ float g_xexp[(size_t)NB * NT * ND];

// ---------------- cluster / async primitives ----------------
__device__ __forceinline__ unsigned cluster_rank() {
    unsigned r;
    asm("mov.u32 %0, %%cluster_ctarank;" : "=r"(r));
    return r;
}
__device__ __forceinline__ void cluster_sync() {
    asm volatile("barrier.cluster.arrive.aligned;" ::: "memory");
    asm volatile("barrier.cluster.wait.aligned;" ::: "memory");
}
__device__ __forceinline__ unsigned mapa_addr(const void* p, int rank) {
    unsigned local = (unsigned)__cvta_generic_to_shared(p);
    unsigned remote;
    asm("mapa.shared::cluster.u32 %0, %1, %2;" : "=r"(remote) : "r"(local), "r"(rank));
    return remote;
}
__device__ __forceinline__ void stc_f32(unsigned addr, float v) {
    asm volatile("st.shared::cluster.f32 [%0], %1;" :: "r"(addr), "f"(v) : "memory");
}
__device__ __forceinline__ void cpa16(void* dst, const void* src) {
    unsigned d = (unsigned)__cvta_generic_to_shared(dst);
    asm volatile("cp.async.cg.shared.global [%0], [%1], 16;" :: "r"(d), "l"(src));
}
__device__ __forceinline__ void mbar_init(void* p, unsigned cnt) {
    asm volatile("mbarrier.init.shared.b64 [%0], %1;"
                 :: "r"((unsigned)__cvta_generic_to_shared(p)), "r"(cnt) : "memory");
}
__device__ __forceinline__ void mbar_arrive_rel_cluster(unsigned remote_addr) {
    asm volatile("mbarrier.arrive.release.cluster.shared::cluster.b64 _, [%0];"
                 :: "r"(remote_addr) : "memory");
}
__device__ __forceinline__ void mbar_wait_acq_cluster(void* p, unsigned parity) {
    unsigned addr = (unsigned)__cvta_generic_to_shared(p);
    asm volatile(
        "{\n\t"
        ".reg .pred P;\n\t"
        "WLOOP%=:\n\t"
        "mbarrier.try_wait.parity.acquire.cluster.shared::cta.b64 P, [%0], %1, 0x989680;\n\t"
        "@P bra WDONE%=;\n\t"
        "bra WLOOP%=;\n\t"
        "WDONE%=:\n\t"
        "}"
        :: "r"(addr), "r"(parity) : "memory");
}

// ---------------- preprocessing ----------------
__global__ void k_exp(const float* __restrict__ x) {
    size_t i = (size_t)blockIdx.x * blockDim.x + threadIdx.x;
    float4 v = __ldg(((const float4*)x) + i);
    float4 o;
    o.x = __expf(fminf(fmaxf(v.x, -30.f), 30.f));
    o.y = __expf(fminf(fmaxf(v.y, -30.f), 30.f));
    o.z = __expf(fminf(fmaxf(v.z, -30.f), 30.f));
    o.w = __expf(fminf(fmaxf(v.w, -30.f), 30.f));
    ((float4*)g_xexp)[i] = o;
}

// block 0: den zero+hist+scan+octile cuts ; blocks 1..32: num per-b
__global__ void __launch_bounds__(1024) k_graph(const int* __restrict__ de_out,
                                                const int* __restrict__ ne_out) {
    __shared__ int cnt[S_DEN];
    __shared__ int pfx[1024];
    int tid = threadIdx.x;
    if (blockIdx.x == 0) {
        for (int s = tid; s < S_DEN; s += 1024) { cnt[s] = 0; g_dfill[s] = 0; }
        __syncthreads();
        for (int j = tid; j < E_DEN; j += 1024) atomicAdd(&cnt[__ldg(de_out + j)], 1);
        __syncthreads();
        int i0 = 2 * tid, i1 = 2 * tid + 1;
        int c0 = (i0 < S_DEN) ? cnt[i0] : 0;
        int c1 = (i1 < S_DEN) ? cnt[i1] : 0;
        int part = c0 + c1;
        pfx[tid] = part;
        __syncthreads();
        for (int off = 1; off < 1024; off <<= 1) {
            int v = pfx[tid];
            if (tid >= off) v += pfx[tid - off];
            __syncthreads();
            pfx[tid] = v;
            __syncthreads();
        }
        int base = pfx[tid] - part;
        if (i0 <= S_DEN) g_drow[i0] = base;
        if (i1 <= S_DEN) g_drow[i1] = base + c0;
        if (tid == 0) g_drow[S_DEN] = E_DEN;
        __syncthreads();
        for (int s = tid; s < S_DEN; s += 1024) {
            int r = g_drow[s];
            int rp = (s == 0) ? -1 : g_drow[s - 1];
            #pragma unroll
            for (int k = 1; k < CS; k++) {
                int target = k * (E_DEN / CS);
                if (r >= target && rp < target) { g_dscut[k] = s; g_decut[k] = r; }
            }
        }
        if (tid == 0) { g_dscut[0] = 0; g_decut[0] = 0; g_dscut[CS] = S_DEN; g_decut[CS] = E_DEN; }
    } else {
        int b = blockIdx.x - 1;
        if (tid < S_NUM) { cnt[tid] = 0; g_nfill[b * S_NUM + tid] = 0; }
        __syncthreads();
        for (int j = tid; j < E_NUM; j += 1024)
            atomicAdd(&cnt[__ldg(ne_out + (size_t)b * E_NUM + j)], 1);
        __syncthreads();
        if (tid < S_NUM) pfx[tid] = cnt[tid];
        __syncthreads();
        for (int off = 1; off < S_NUM; off <<= 1) {
            int v = 0;
            if (tid < S_NUM) { v = pfx[tid]; if (tid >= off) v += pfx[tid - off]; }
            __syncthreads();
            if (tid < S_NUM) pfx[tid] = v;
            __syncthreads();
        }
        if (tid < S_NUM) {
            int excl = pfx[tid] - cnt[tid];
            g_nrow[b * (S_NUM + 1) + tid] = excl;
            if (tid == S_NUM - 1) g_nrow[b * (S_NUM + 1) + S_NUM] = E_NUM;
            #pragma unroll
            for (int k = 1; k < CS; k++) {
                int target = k * (E_NUM / CS);
                int exclp = (tid == 0) ? -1 : (pfx[tid - 1] - cnt[tid - 1]);
                if (excl >= target && exclp < target) {
                    g_nscut[b * (CS + 1) + k] = tid;
                    g_necut[b * (CS + 1) + k] = excl;
                }
            }
            if (tid == 0) {
                g_nscut[b * (CS + 1)] = 0; g_necut[b * (CS + 1)] = 0;
                g_nscut[b * (CS + 1) + CS] = S_NUM; g_necut[b * (CS + 1) + CS] = E_NUM;
            }
        }
    }
}

__global__ void k_scatter(const int* __restrict__ de_in, const int* __restrict__ de_out,
                          const int* __restrict__ de_pdf, const float* __restrict__ de_prob,
                          const int* __restrict__ ne_in, const int* __restrict__ ne_out,
                          const int* __restrict__ ne_pdf, const float* __restrict__ ne_prob) {
    int i = blockIdx.x * blockDim.x + threadIdx.x;
    if (i < E_DEN) {
        int out = de_out[i];
        int p = atomicAdd(&g_dfill[out], 1);
        int pos = g_drow[out] + p;
        unsigned flag = (pos + 1 == g_drow[out + 1]) ? 1u : 0u;
        unsigned pack = (unsigned)de_in[i] | ((unsigned)de_pdf[i] << 11) | (flag << 22);
        g_dedge[pos] = make_uint2(pack, __float_as_uint(de_prob[i]));
        g_dout[pos] = (unsigned short)out;
    }
    if (i < NB * E_NUM) {
        int b = i >> 11;
        int out = ne_out[i];
        int p = atomicAdd(&g_nfill[b * S_NUM + out], 1);
        int pos = g_nrow[b * (S_NUM + 1) + out] + p;
        unsigned flag = (pos + 1 == g_nrow[b * (S_NUM + 1) + out + 1]) ? 1u : 0u;
        unsigned pack = (unsigned)ne_in[i] | ((unsigned)ne_pdf[i] << 11) | (flag << 22);
        g_nedge[b * E_NUM + pos] = make_uint2(pack, __float_as_uint(ne_prob[i]));
        g_nout[b * E_NUM + pos] = (unsigned short)out;
    }
}

// ---------------- main recursion: 1 cluster (8 CTAs) per 2 utterances ----------------
__global__ void __cluster_dims__(CS, 1, 1) __launch_bounds__(1024, 1)
k_main(const int* __restrict__ xlen,
       const float* __restrict__ dleaky, const float* __restrict__ dfinal,
       const float* __restrict__ nleaky, const float* __restrict__ nfinal) {
    extern __shared__ char sm[];
    float* AD   = (float*)(sm + OFF_AD);      // [2][S_DEN]
    float* CLD  = (float*)(sm + OFF_CLD);
    float* XT   = (float*)(sm + OFF_XT);      // [2][ND]
    float* AN   = (float*)(sm + OFF_AN);      // [2][S_NUM]
    float* CLN  = (float*)(sm + OFF_CLN);
    float* AW   = (float*)(sm + OFF_AW);
    float* AWN  = (float*)(sm + OFF_AWN);
    uint2* NE   = (uint2*)(sm + OFF_NE);
    unsigned short* NDST = (unsigned short*)(sm + OFF_ND);
    float* SRD  = (float*)(sm + OFF_SRD);
    float* SRN  = (float*)(sm + OFF_SRN);
    float* MAILD = (float*)(sm + OFF_MAILD);  // [2][CS]
    float* MAILN = (float*)(sm + OFF_MAILN);  // [2][CS]
    unsigned long long* MB = (unsigned long long*)(sm + OFF_MBAR);  // [2] ping-pong
    float* DPR  = (float*)(sm + OFF_DPR);     // [DPER*1024]
    unsigned short* DDS = (unsigned short*)(sm + OFF_DDS);

    const int rank = (int)cluster_rank();
    const int c = (int)(blockIdx.x >> 3);
    const int tid = threadIdx.x;
    const int lane = tid & 31, wid = tid >> 5;

    // ---- den slice (shared graph; loop + utterance invariant) ----
    const int de0 = g_decut[rank], de1 = g_decut[rank + 1];
    const int ds0 = g_dscut[rank], ds1 = g_dscut[rank + 1];
    const int dn = de1 - de0;
    const unsigned short dl = __ldg(&g_dout[de1 - 1]);
    unsigned epack[DPER];
    #pragma unroll
    for (int k = 0; k < DPER; k++) {
        int j = tid * DPER + k;
        if (j < dn) {
            uint2 w = __ldg(&g_dedge[de0 + j]);
            epack[k] = w.x;
            DPR[k * 1024 + tid] = __uint_as_float(w.y);
            DDS[k * 1024 + tid] = __ldg(&g_dout[de0 + j]);
        } else {
            epack[k] = 0u;
            DPR[k * 1024 + tid] = 0.0f;
            DDS[k * 1024 + tid] = dl;
        }
    }
    for (int s = tid; s < S_DEN; s += 1024) {
        CLD[s] = 1e-5f * __ldg(dleaky + s);
        AW[s] = 0.0f;
    }
    if (tid < S_NUM) AWN[tid] = 0.0f;
    if (tid == 0) { mbar_init(&MB[0], CS); mbar_init(&MB[1], CS); }

    cluster_sync();   // mbar init + cuts visible cluster-wide before any arrive

    unsigned gt = 0;  // global sync index (continues across both utterances)

    for (int u = 0; u < 2; ++u) {
        const int b = (u == 0) ? c : (NB - 1 - c);

        // ---- per-utterance init (buffer 0 only; frame-0 broadcast targets buffer 1) ----
        for (int s = tid; s < S_DEN; s += 1024)
            AD[s] = CLD[s] + (s == 0 ? 1.0f : 0.0f);
        if (tid < S_NUM) {
            float cl = 1e-20f * __ldg(nleaky + b * S_NUM + tid);
            CLN[tid] = cl;
            AN[tid] = cl + (tid == 0 ? 1.0f : 0.0f);
        }
        const int ne0 = g_necut[b * (CS + 1) + rank], ne1 = g_necut[b * (CS + 1) + rank + 1];
        const int ns0 = g_nscut[b * (CS + 1) + rank], ns1 = g_nscut[b * (CS + 1) + rank + 1];
        const int nn = ne1 - ne0;
        if (tid < nn) {
            NE[tid] = __ldg(&g_nedge[(size_t)b * E_NUM + ne0 + tid]);
            NDST[tid] = __ldg(&g_nout[(size_t)b * E_NUM + ne0 + tid]);
        }

        const int len = xlen[b];
        const float* xe = g_xexp + (size_t)b * NT * ND;

        // frame 0 -> XT[0]
        if (tid < 512) cpa16(XT + tid * 4, xe + tid * 4);
        asm volatile("cp.async.commit_group;" ::: "memory");
        asm volatile("cp.async.wait_group 0;" ::: "memory");
        __syncthreads();   // local init + XT[0] visible

        float lzd = 0.0f, lzn = 0.0f;

        for (int t = 0; t < len; ++t, ++gt) {
            const int buf = t & 1, nb = buf ^ 1;

            if (t + 1 < len && tid < 512)
                cpa16(XT + nb * ND + tid * 4, xe + (size_t)(t + 1) * ND + tid * 4);
            asm volatile("cp.async.commit_group;" ::: "memory");

            const float* ab  = AD + buf * S_DEN;
            const float* xtb = XT + buf * ND;

            // ---- den gather ----
            float ssum = 0.0f;
            if (tid * DPER < dn) {
                float acc = 0.0f;
                #pragma unroll
                for (int k = 0; k < DPER; k++) {
                    const unsigned w = epack[k];
                    float p = DPR[k * 1024 + tid];
                    float av = ab[w & 2047u];
                    float xv = xtb[(w >> 11) & 2047u];
                    acc = fmaf(av * xv, p, acc);
                    if (w & (1u << 22)) {
                        atomicAdd(&AW[DDS[k * 1024 + tid]], acc);
                        ssum += acc;
                        acc = 0.0f;
                    }
                }
                if (acc != 0.0f) {
                    atomicAdd(&AW[DDS[(DPER - 1) * 1024 + tid]], acc);
                    ssum += acc;
                }
            }
            // ---- num gather (<=1 edge/thread) ----
            float nsum = 0.0f;
            if (tid < nn) {
                uint2 w = NE[tid];
                float av = AN[buf * S_NUM + (w.x & 2047u)];
                float xv = xtb[(w.x >> 11) & 2047u];
                float nacc = av * xv * __uint_as_float(w.y);
                atomicAdd(&AWN[NDST[tid]], nacc);
                nsum = nacc;
            }

            // ---- two-level reduction ----
            #pragma unroll
            for (int o = 16; o; o >>= 1) {
                ssum += __shfl_xor_sync(0xffffffffu, ssum, o);
                nsum += __shfl_xor_sync(0xffffffffu, nsum, o);
            }
            if (lane == 0) { SRD[wid] = ssum; SRN[wid] = nsum; }
            __syncthreads();   // AW/AWN/SRD/SRN complete

            if (tid < 32) {
                float v = SRD[tid];
                #pragma unroll
                for (int o = 16; o; o >>= 1) v += __shfl_xor_sync(0xffffffffu, v, o);
                if (tid == 0) {
                    MAILD[buf * CS + rank] = v;
                    unsigned moff = 4u * (unsigned)(buf * CS + rank);
                    #pragma unroll
                    for (int k = 0; k < CS; k++)
                        if (k != rank) stc_f32(mapa_addr(MAILD, k) + moff, v);
                }
            } else if (tid < 64) {
                float v = SRN[lane];
                #pragma unroll
                for (int o = 16; o; o >>= 1) v += __shfl_xor_sync(0xffffffffu, v, o);
                if (lane == 0) {
                    MAILN[buf * CS + rank] = v;
                    unsigned moff = 4u * (unsigned)(buf * CS + rank);
                    #pragma unroll
                    for (int k = 0; k < CS; k++)
                        if (k != rank) stc_f32(mapa_addr(MAILN, k) + moff, v);
                }
            }

            // ---- broadcast RAW anew slices into alpha[nb] of all ranks ----
            for (int s = ds0 + tid; s < ds1; s += 1024) {
                float v = AW[s];
                AW[s] = 0.0f;
                AD[nb * S_DEN + s] = v;   // self: local store
                unsigned off = 4u * (unsigned)(nb * S_DEN + s);
                #pragma unroll
                for (int k = 0; k < CS; k++)
                    if (k != rank) stc_f32(mapa_addr(AD, k) + off, v);
            }
            for (int s = ns0 + tid; s < ns1; s += 1024) {
                float v = AWN[s];
                AWN[s] = 0.0f;
                AN[nb * S_NUM + s] = v;
                unsigned off = 4u * (unsigned)(nb * S_NUM + s);
                #pragma unroll
                for (int k = 0; k < CS; k++)
                    if (k != rank) stc_f32(mapa_addr(AN, k) + off, v);
            }
            __syncthreads();   // all lanes' stores ordered before tid<8's release-arrives

            // ---- ping-pong cluster barrier: frame gt uses MB[gt&1], parity (gt>>1)&1 ----
            {
                const unsigned bi = gt & 1u;
                if (tid < CS)
                    mbar_arrive_rel_cluster(mapa_addr((void*)&MB[bi], tid));
                mbar_wait_acq_cluster((void*)&MB[bi], (gt >> 1) & 1u);
            }

            // ---- everyone computes asum locally; normalize local replica ----
            float asd = 0.0f, asn = 0.0f;
            #pragma unroll
            for (int k = 0; k < CS; k++) {
                asd += MAILD[buf * CS + k];
                asn += MAILN[buf * CS + k];
            }
            float invd = 1.0f / asd;
            float invn = 1.0f / asn;
            if (rank == 0 && tid == 0) { lzd += __logf(asd); lzn += __logf(asn); }

            float* adn = AD + nb * S_DEN;
            float* ann = AN + nb * S_NUM;
            for (int s = tid; s < S_DEN; s += 1024) adn[s] = fmaf(adn[s], invd, CLD[s]);
            if (tid < S_NUM) ann[tid] = fmaf(ann[tid], invn, CLN[tid]);

            asm volatile("cp.async.wait_group 0;" ::: "memory");
            __syncthreads();   // normalize + XT[nb] visible locally
        }

        // ---- per-utterance objf on rank 0: stage sums, write BOTH at tid 0 (valid lzd/lzn) ----
        if (rank == 0) {
            const int fb = len & 1;
            float fd = 0.0f, fn = 0.0f;
            for (int s = tid; s < S_DEN; s += 1024) fd += AD[fb * S_DEN + s] * __ldg(dfinal + s);
            for (int s = tid; s < S_NUM; s += 1024) fn += AN[fb * S_NUM + s] * __ldg(nfinal + b * S_NUM + s);
            #pragma unroll
            for (int o = 16; o; o >>= 1) {
                fd += __shfl_xor_sync(0xffffffffu, fd, o);
                fn += __shfl_xor_sync(0xffffffffu, fn, o);
            }
            if (lane == 0) { SRD[wid] = fd; SRN[wid] = fn; }
            __syncthreads();
            if (tid < 32) {
                float v = SRD[tid];
                #pragma unroll
                for (int o = 16; o; o >>= 1) v += __shfl_xor_sync(0xffffffffu, v, o);
                if (tid == 0) SRD[0] = v;
            } else if (tid < 64) {
                float v = SRN[lane];
                #pragma unroll
                for (int o = 16; o; o >>= 1) v += __shfl_xor_sync(0xffffffffu, v, o);
                if (lane == 0) SRN[0] = v;
            }
            __syncthreads();
            if (tid == 0) {
                g_objd[b] = lzd + logf(SRD[0]);   // lzd/lzn live on tid 0 only
                g_objn[b] = lzn + logf(SRN[0]);
            }
            __syncthreads();
        }
    }
}

__global__ void k_final(const int* __restrict__ xlen, float* __restrict__ out) {
    int tid = threadIdx.x;  // 32 threads
    float d = g_objd[tid];
    float n = g_objn[tid];
    float l = (float)xlen[tid];
    #pragma unroll
    for (int o = 16; o; o >>= 1) {
        d += __shfl_xor_sync(0xffffffffu, d, o);
        n += __shfl_xor_sync(0xffffffffu, n, o);
        l += __shfl_xor_sync(0xffffffffu, l, o);
    }
    if (tid == 0) out[0] = -(n - d) / l;
}

// ---------------- launch ----------------
extern "C" void kernel_launch(void* const* d_in, const int* in_sizes, int n_in,
                              void* d_out, int out_size) {
    const float* x = (const float*)d_in[0];
    const int* xlen = (const int*)d_in[1];
    const int* de_in = (const int*)d_in[2];
    const int* de_out = (const int*)d_in[3];
    const int* de_pdf = (const int*)d_in[4];
    const float* de_prob = (const float*)d_in[5];
    const float* dleaky = (const float*)d_in[6];
    const float* dfinal = (const float*)d_in[7];
    const int* ne_in = (const int*)d_in[8];
    const int* ne_out = (const int*)d_in[9];
    const int* ne_pdf = (const int*)d_in[10];
    const float* ne_prob = (const float*)d_in[11];
    const float* nleaky = (const float*)d_in[12];
    const float* nfinal = (const float*)d_in[13];
    float* out = (float*)d_out;

    cudaFuncSetAttribute(k_main, cudaFuncAttributeMaxDynamicSharedMemorySize, SMEM_MAIN);

    k_exp<<<(NB * NT * ND / 4 + 1023) / 1024, 1024>>>(x);                 // launch 0
    k_graph<<<NB + 1, 1024>>>(de_out, ne_out);                            // launch 1
    k_scatter<<<256, 256>>>(de_in, de_out, de_pdf, de_prob,
                            ne_in, ne_out, ne_pdf, ne_prob);              // launch 2
    k_main<<<NCL * CS, 1024, SMEM_MAIN>>>(xlen, dleaky, dfinal, nleaky, nfinal); // launch 3 (ncu)
    k_final<<<1, 32>>>(xlen, out);                                        // launch 4
}

// round 14
// speedup vs baseline: 2.1694x; 2.1694x over previous
#include <cuda_runtime.h>
#include <cstdint>

#define NB 32
#define NT 400
#define ND 2048
#define S_DEN 2000
#define E_DEN 60000
#define S_NUM 512
#define E_NUM 2048
#define CS 4          // cluster size
#define DPER 15       // den edges per thread (~15000/1024 -> 15)

// ---- dynamic smem layout (bytes) ----
#define OFF_AD    0        // float[2][S_DEN]        16000 (16B aligned)
#define OFF_CLD   16000    // float[S_DEN]            8000 (16B aligned)
#define OFF_XT    24000    // float[2][ND]           16384 (16B aligned)
#define OFF_AN    40384    // float[2][S_NUM]         4096 (16B aligned)
#define OFF_CLN   44480    // float[S_NUM]            2048 (16B aligned)
#define OFF_AW    46528    // float[S_DEN]            8000 (16B aligned)
#define OFF_AWN   54528    // float[S_NUM]            2048 (16B aligned)
#define OFF_NE    56576    // uint2[1024]             8192
#define OFF_ND    64768    // u16[1024]               2048
#define OFF_SRD   66816    // float[32]                128
#define OFF_SRN   66944    // float[32]                128
#define OFF_MAILD 67072    // float[2][CS]              32
#define OFF_MAILN 67104    // float[2][CS]              32
#define OFF_MBAR  67136    // u64[2] ping-pong          16
#define OFF_DPR   67152    // float[DPER*1024]       61440
#define OFF_DDS   128592   // u16[DPER*1024]         30720
#define SMEM_MAIN 159360

// ---------------- device scratch ----------------
__device__ int g_dfill[S_DEN];
__device__ int g_drow[S_DEN + 1];
__device__ uint2 g_dedge[E_DEN];
__device__ unsigned short g_dout[E_DEN];
__device__ int g_dscut[CS + 1];
__device__ int g_decut[CS + 1];

__device__ int g_nfill[NB * S_NUM];
__device__ int g_nrow[NB * (S_NUM + 1)];
__device__ uint2 g_nedge[NB * E_NUM];
__device__ unsigned short g_nout[NB * E_NUM];
__device__ int g_nscut[NB * (CS + 1)];
__device__ int g_necut[NB * (CS + 1)];

__device__ float g_objd[NB];
__device__ float g_objn[NB];

__device__ float g_xexp[(size_t)NB * NT * ND];

// ---------------- cluster / async primitives ----------------
__device__ __forceinline__ unsigned cluster_rank() {
    unsigned r;
    asm("mov.u32 %0, %%cluster_ctarank;" : "=r"(r));
    return r;
}
__device__ __forceinline__ void cluster_sync() {
    asm volatile("barrier.cluster.arrive.aligned;" ::: "memory");
    asm volatile("barrier.cluster.wait.aligned;" ::: "memory");
}
__device__ __forceinline__ unsigned mapa_addr(const void* p, int rank) {
    unsigned local = (unsigned)__cvta_generic_to_shared(p);
    unsigned remote;
    asm("mapa.shared::cluster.u32 %0, %1, %2;" : "=r"(remote) : "r"(local), "r"(rank));
    return remote;
}
__device__ __forceinline__ void stc_f32(unsigned addr, float v) {
    asm volatile("st.shared::cluster.f32 [%0], %1;" :: "r"(addr), "f"(v) : "memory");
}
__device__ __forceinline__ void stc_f32x4(unsigned addr, float4 v) {
    asm volatile("st.shared::cluster.v4.f32 [%0], {%1, %2, %3, %4};"
                 :: "r"(addr), "f"(v.x), "f"(v.y), "f"(v.z), "f"(v.w) : "memory");
}
__device__ __forceinline__ void cpa16(void* dst, const void* src) {
    unsigned d = (unsigned)__cvta_generic_to_shared(dst);
    asm volatile("cp.async.cg.shared.global [%0], [%1], 16;" :: "r"(d), "l"(src));
}
__device__ __forceinline__ void mbar_init(void* p, unsigned cnt) {
    asm volatile("mbarrier.init.shared.b64 [%0], %1;"
                 :: "r"((unsigned)__cvta_generic_to_shared(p)), "r"(cnt) : "memory");
}
__device__ __forceinline__ void mbar_arrive_rel_cluster(unsigned remote_addr) {
    asm volatile("mbarrier.arrive.release.cluster.shared::cluster.b64 _, [%0];"
                 :: "r"(remote_addr) : "memory");
}
__device__ __forceinline__ void mbar_wait_acq_cluster(void* p, unsigned parity) {
    unsigned addr = (unsigned)__cvta_generic_to_shared(p);
    asm volatile(
        "{\n\t"
        ".reg .pred P;\n\t"
        "WLOOP%=:\n\t"
        "mbarrier.try_wait.parity.acquire.cluster.shared::cta.b64 P, [%0], %1, 0x989680;\n\t"
        "@P bra WDONE%=;\n\t"
        "bra WLOOP%=;\n\t"
        "WDONE%=:\n\t"
        "}"
        :: "r"(addr), "r"(parity) : "memory");
}

// ---------------- preprocessing ----------------
__global__ void k_exp(const float* __restrict__ x) {
    size_t i = (size_t)blockIdx.x * blockDim.x + threadIdx.x;
    float4 v = __ldg(((const float4*)x) + i);
    float4 o;
    o.x = __expf(fminf(fmaxf(v.x, -30.f), 30.f));
    o.y = __expf(fminf(fmaxf(v.y, -30.f), 30.f));
    o.z = __expf(fminf(fmaxf(v.z, -30.f), 30.f));
    o.w = __expf(fminf(fmaxf(v.w, -30.f), 30.f));
    ((float4*)g_xexp)[i] = o;
}

// block 0: den zero+hist+scan+cuts (4-state aligned) ; blocks 1..32: num per-b
__global__ void __launch_bounds__(1024) k_graph(const int* __restrict__ de_out,
                                                const int* __restrict__ ne_out) {
    __shared__ int cnt[S_DEN];
    __shared__ int pfx[1024];
    int tid = threadIdx.x;
    if (blockIdx.x == 0) {
        for (int s = tid; s < S_DEN; s += 1024) { cnt[s] = 0; g_dfill[s] = 0; }
        __syncthreads();
        for (int j = tid; j < E_DEN; j += 1024) atomicAdd(&cnt[__ldg(de_out + j)], 1);
        __syncthreads();
        int i0 = 2 * tid, i1 = 2 * tid + 1;
        int c0 = (i0 < S_DEN) ? cnt[i0] : 0;
        int c1 = (i1 < S_DEN) ? cnt[i1] : 0;
        int part = c0 + c1;
        pfx[tid] = part;
        __syncthreads();
        for (int off = 1; off < 1024; off <<= 1) {
            int v = pfx[tid];
            if (tid >= off) v += pfx[tid - off];
            __syncthreads();
            pfx[tid] = v;
            __syncthreads();
        }
        int base = pfx[tid] - part;
        if (i0 <= S_DEN) g_drow[i0] = base;
        if (i1 <= S_DEN) g_drow[i1] = base + c0;
        if (tid == 0) g_drow[S_DEN] = E_DEN;
        __syncthreads();
        for (int s = tid; s < S_DEN; s += 1024) {
            int r = g_drow[s];
            int rp = (s == 0) ? -1 : g_drow[s - 1];
            #pragma unroll
            for (int k = 1; k < CS; k++) {
                int target = k * (E_DEN / CS);
                if (r >= target && rp < target) {
                    int sa = s & ~3;           // 4-state aligned for vec4 broadcast
                    g_dscut[k] = sa;
                    g_decut[k] = g_drow[sa];
                }
            }
        }
        if (tid == 0) { g_dscut[0] = 0; g_decut[0] = 0; g_dscut[CS] = S_DEN; g_decut[CS] = E_DEN; }
    } else {
        int b = blockIdx.x - 1;
        if (tid < S_NUM) { cnt[tid] = 0; g_nfill[b * S_NUM + tid] = 0; }
        __syncthreads();
        for (int j = tid; j < E_NUM; j += 1024)
            atomicAdd(&cnt[__ldg(ne_out + (size_t)b * E_NUM + j)], 1);
        __syncthreads();
        if (tid < S_NUM) pfx[tid] = cnt[tid];
        __syncthreads();
        for (int off = 1; off < S_NUM; off <<= 1) {
            int v = 0;
            if (tid < S_NUM) { v = pfx[tid]; if (tid >= off) v += pfx[tid - off]; }
            __syncthreads();
            if (tid < S_NUM) pfx[tid] = v;
            __syncthreads();
        }
        if (tid < S_NUM) {
            int excl = pfx[tid] - cnt[tid];
            g_nrow[b * (S_NUM + 1) + tid] = excl;
            if (tid == S_NUM - 1) g_nrow[b * (S_NUM + 1) + S_NUM] = E_NUM;
        }
        __syncthreads();
        if (tid < S_NUM) {
            int excl = g_nrow[b * (S_NUM + 1) + tid];
            int exclp = (tid == 0) ? -1 : g_nrow[b * (S_NUM + 1) + tid - 1];
            #pragma unroll
            for (int k = 1; k < CS; k++) {
                int target = k * (E_NUM / CS);
                if (excl >= target && exclp < target) {
                    int sa = tid & ~3;
                    g_nscut[b * (CS + 1) + k] = sa;
                    g_necut[b * (CS + 1) + k] = g_nrow[b * (S_NUM + 1) + sa];
                }
            }
            if (tid == 0) {
                g_nscut[b * (CS + 1)] = 0; g_necut[b * (CS + 1)] = 0;
                g_nscut[b * (CS + 1) + CS] = S_NUM; g_necut[b * (CS + 1) + CS] = E_NUM;
            }
        }
    }
}

__global__ void k_scatter(const int* __restrict__ de_in, const int* __restrict__ de_out,
                          const int* __restrict__ de_pdf, const float* __restrict__ de_prob,
                          const int* __restrict__ ne_in, const int* __restrict__ ne_out,
                          const int* __restrict__ ne_pdf, const float* __restrict__ ne_prob) {
    int i = blockIdx.x * blockDim.x + threadIdx.x;
    if (i < E_DEN) {
        int out = de_out[i];
        int p = atomicAdd(&g_dfill[out], 1);
        int pos = g_drow[out] + p;
        unsigned flag = (pos + 1 == g_drow[out + 1]) ? 1u : 0u;
        unsigned pack = (unsigned)de_in[i] | ((unsigned)de_pdf[i] << 11) | (flag << 22);
        g_dedge[pos] = make_uint2(pack, __float_as_uint(de_prob[i]));
        g_dout[pos] = (unsigned short)out;
    }
    if (i < NB * E_NUM) {
        int b = i >> 11;
        int out = ne_out[i];
        int p = atomicAdd(&g_nfill[b * S_NUM + out], 1);
        int pos = g_nrow[b * (S_NUM + 1) + out] + p;
        unsigned flag = (pos + 1 == g_nrow[b * (S_NUM + 1) + out + 1]) ? 1u : 0u;
        unsigned pack = (unsigned)ne_in[i] | ((unsigned)ne_pdf[i] << 11) | (flag << 22);
        g_nedge[b * E_NUM + pos] = make_uint2(pack, __float_as_uint(ne_prob[i]));
        g_nout[b * E_NUM + pos] = (unsigned short)out;
    }
}

// ---------------- main recursion: 1 cluster (4 CTAs) per utterance ----------------
__global__ void __cluster_dims__(CS, 1, 1) __launch_bounds__(1024, 1)
k_main(const int* __restrict__ xlen,
       const float* __restrict__ dleaky, const float* __restrict__ dfinal,
       const float* __restrict__ nleaky, const float* __restrict__ nfinal) {
    extern __shared__ char sm[];
    float* AD   = (float*)(sm + OFF_AD);      // [2][S_DEN]
    float* CLD  = (float*)(sm + OFF_CLD);
    float* XT   = (float*)(sm + OFF_XT);      // [2][ND]
    float* AN   = (float*)(sm + OFF_AN);      // [2][S_NUM]
    float* CLN  = (float*)(sm + OFF_CLN);
    float* AW   = (float*)(sm + OFF_AW);
    float* AWN  = (float*)(sm + OFF_AWN);
    uint2* NE   = (uint2*)(sm + OFF_NE);
    unsigned short* NDST = (unsigned short*)(sm + OFF_ND);
    float* SRD  = (float*)(sm + OFF_SRD);
    float* SRN  = (float*)(sm + OFF_SRN);
    float* MAILD = (float*)(sm + OFF_MAILD);  // [2][CS]
    float* MAILN = (float*)(sm + OFF_MAILN);  // [2][CS]
    unsigned long long* MB = (unsigned long long*)(sm + OFF_MBAR);  // [2]
    float* DPR  = (float*)(sm + OFF_DPR);     // [DPER*1024]
    unsigned short* DDS = (unsigned short*)(sm + OFF_DDS);

    const int rank = (int)cluster_rank();
    const int b = (int)(blockIdx.x >> 2);
    const int tid = threadIdx.x;
    const int lane = tid & 31, wid = tid >> 5;

    // ---- den slice (shared graph) ----
    const int de0 = g_decut[rank], de1 = g_decut[rank + 1];
    const int ds0 = g_dscut[rank], ds1 = g_dscut[rank + 1];
    const int dn = de1 - de0;
    const unsigned short dl = __ldg(&g_dout[de1 - 1]);
    unsigned epack[DPER];
    #pragma unroll
    for (int k = 0; k < DPER; k++) {
        int j = tid * DPER + k;
        if (j < dn) {
            uint2 w = __ldg(&g_dedge[de0 + j]);
            epack[k] = w.x;
            DPR[k * 1024 + tid] = __uint_as_float(w.y);
            DDS[k * 1024 + tid] = __ldg(&g_dout[de0 + j]);
        } else {
            epack[k] = 0u;
            DPR[k * 1024 + tid] = 0.0f;
            DDS[k * 1024 + tid] = dl;
        }
    }
    for (int s = tid; s < S_DEN; s += 1024) {
        float cl = 1e-5f * __ldg(dleaky + s);
        CLD[s] = cl;
        AD[s] = cl + (s == 0 ? 1.0f : 0.0f);
        AW[s] = 0.0f;
    }
    if (tid < S_NUM) {
        float cl = 1e-20f * __ldg(nleaky + b * S_NUM + tid);
        CLN[tid] = cl;
        AN[tid] = cl + (tid == 0 ? 1.0f : 0.0f);
        AWN[tid] = 0.0f;
    }
    // ---- num slice ----
    const int ne0 = g_necut[b * (CS + 1) + rank], ne1 = g_necut[b * (CS + 1) + rank + 1];
    const int ns0 = g_nscut[b * (CS + 1) + rank], ns1 = g_nscut[b * (CS + 1) + rank + 1];
    const int nn = ne1 - ne0;            // <= ~540, one edge per thread
    if (tid < nn) {
        NE[tid] = __ldg(&g_nedge[(size_t)b * E_NUM + ne0 + tid]);
        NDST[tid] = __ldg(&g_nout[(size_t)b * E_NUM + ne0 + tid]);
    }
    if (tid == 0) { mbar_init(&MB[0], CS); mbar_init(&MB[1], CS); }

    // remote addresses (registers, loop-invariant)
    unsigned adr[CS], anr[CS], mdr[CS], mnr[CS], mbr0[CS], mbr1[CS];
    #pragma unroll
    for (int k = 0; k < CS; k++) {
        adr[k] = mapa_addr(AD, k);
        anr[k] = mapa_addr(AN, k);
        mdr[k] = mapa_addr(MAILD, k);
        mnr[k] = mapa_addr(MAILN, k);
        mbr0[k] = mapa_addr((void*)&MB[0], k);
        mbr1[k] = mapa_addr((void*)&MB[1], k);
    }

    const int len = xlen[b];
    const float* xe = g_xexp + (size_t)b * NT * ND;

    // frame 0 -> XT[0]
    if (tid < 512) cpa16(XT + tid * 4, xe + tid * 4);
    asm volatile("cp.async.commit_group;" ::: "memory");
    asm volatile("cp.async.wait_group 0;" ::: "memory");
    __syncthreads();
    cluster_sync();   // mbar init + all init visible cluster-wide

    float lzd = 0.0f, lzn = 0.0f;

    for (int t = 0; t < len; ++t) {
        const int buf = t & 1, nb = buf ^ 1;

        if (t + 1 < len && tid < 512)
            cpa16(XT + nb * ND + tid * 4, xe + (size_t)(t + 1) * ND + tid * 4);
        asm volatile("cp.async.commit_group;" ::: "memory");

        const float* ab  = AD + buf * S_DEN;
        const float* xtb = XT + buf * ND;

        // ---- den gather (pack in regs, prob conflict-free LDS) ----
        float ssum = 0.0f;
        {
            float acc = 0.0f;
            #pragma unroll
            for (int k = 0; k < DPER; k++) {
                const unsigned w = epack[k];
                float p = DPR[k * 1024 + tid];
                float av = ab[w & 2047u];
                float xv = xtb[(w >> 11) & 2047u];
                acc = fmaf(av * xv, p, acc);
                if (w & (1u << 22)) {
                    atomicAdd(&AW[DDS[k * 1024 + tid]], acc);
                    ssum += acc;
                    acc = 0.0f;
                }
            }
            if (acc != 0.0f) { atomicAdd(&AW[DDS[(DPER - 1) * 1024 + tid]], acc); ssum += acc; }
        }
        // ---- num gather (1 edge/thread) ----
        float nsum = 0.0f;
        if (tid < nn) {
            uint2 w = NE[tid];
            float av = AN[buf * S_NUM + (w.x & 2047u)];
            float xv = xtb[(w.x >> 11) & 2047u];
            float nacc = av * xv * __uint_as_float(w.y);
            atomicAdd(&AWN[NDST[tid]], nacc);
            nsum = nacc;
        }

        // ---- two-level reduction ----
        #pragma unroll
        for (int o = 16; o; o >>= 1) {
            ssum += __shfl_xor_sync(0xffffffffu, ssum, o);
            nsum += __shfl_xor_sync(0xffffffffu, nsum, o);
        }
        if (lane == 0) { SRD[wid] = ssum; SRN[wid] = nsum; }
        __syncthreads();   // #1: AW/AWN/SRD/SRN complete

        if (tid < 32) {
            float v = SRD[tid];
            #pragma unroll
            for (int o = 16; o; o >>= 1) v += __shfl_xor_sync(0xffffffffu, v, o);
            if (tid == 0) {
                MAILD[buf * CS + rank] = v;
                unsigned moff = 4u * (unsigned)(buf * CS + rank);
                #pragma unroll
                for (int k = 0; k < CS; k++)
                    if (k != rank) stc_f32(mdr[k] + moff, v);
            }
        } else if (tid < 64) {
            float v = SRN[lane];
            #pragma unroll
            for (int o = 16; o; o >>= 1) v += __shfl_xor_sync(0xffffffffu, v, o);
            if (lane == 0) {
                MAILN[buf * CS + rank] = v;
                unsigned moff = 4u * (unsigned)(buf * CS + rank);
                #pragma unroll
                for (int k = 0; k < CS; k++)
                    if (k != rank) stc_f32(mnr[k] + moff, v);
            }
        }

        // ---- vec4 broadcast of RAW anew slices into alpha[nb] of all ranks ----
        {
            float4* AW4 = (float4*)AW;
            float4* AD4 = (float4*)AD;
            const int q0 = ds0 >> 2, q1 = ds1 >> 2;
            for (int q = q0 + tid; q < q1; q += 1024) {
                float4 v = AW4[q];
                AW4[q] = make_float4(0.f, 0.f, 0.f, 0.f);
                const int dst = nb * (S_DEN / 4) + q;
                AD4[dst] = v;   // self: local store
                unsigned off = 16u * (unsigned)dst;
                #pragma unroll
                for (int k = 0; k < CS; k++)
                    if (k != rank) stc_f32x4(adr[k] + off, v);
            }
            float4* AWN4 = (float4*)AWN;
            float4* AN4 = (float4*)AN;
            const int p0 = ns0 >> 2, p1 = ns1 >> 2;
            for (int q = p0 + tid; q < p1; q += 1024) {
                float4 v = AWN4[q];
                AWN4[q] = make_float4(0.f, 0.f, 0.f, 0.f);
                const int dst = nb * (S_NUM / 4) + q;
                AN4[dst] = v;
                unsigned off = 16u * (unsigned)dst;
                #pragma unroll
                for (int k = 0; k < CS; k++)
                    if (k != rank) stc_f32x4(anr[k] + off, v);
            }
        }
        __syncthreads();   // #2: all lanes' stores ordered before the release-arrives

        // ---- ping-pong cluster barrier: frame t uses MB[t&1], parity (t>>1)&1 ----
        {
            const unsigned bi = (unsigned)buf;
            if (tid < CS) mbar_arrive_rel_cluster(bi ? mbr1[tid] : mbr0[tid]);
            if (tid < 32) mbar_wait_acq_cluster((void*)&MB[bi], ((unsigned)t >> 1) & 1u);
        }
        __syncthreads();   // #3: warp0's acquire fans out to whole CTA

        // ---- asum locally; vec4 normalize local replica ----
        float asd = MAILD[buf * CS + 0] + MAILD[buf * CS + 1] + MAILD[buf * CS + 2] + MAILD[buf * CS + 3];
        float asn = MAILN[buf * CS + 0] + MAILN[buf * CS + 1] + MAILN[buf * CS + 2] + MAILN[buf * CS + 3];
        float invd = 1.0f / asd;
        float invn = 1.0f / asn;
        if (rank == 0 && tid == 0) { lzd += __logf(asd); lzn += __logf(asn); }

        {
            float4* adn4 = (float4*)(AD + nb * S_DEN);
            const float4* cld4 = (const float4*)CLD;
            for (int q = tid; q < S_DEN / 4; q += 1024) {
                float4 v = adn4[q], c = cld4[q];
                v.x = fmaf(v.x, invd, c.x);
                v.y = fmaf(v.y, invd, c.y);
                v.z = fmaf(v.z, invd, c.z);
                v.w = fmaf(v.w, invd, c.w);
                adn4[q] = v;
            }
            float4* ann4 = (float4*)(AN + nb * S_NUM);
            const float4* cln4 = (const float4*)CLN;
            if (tid < S_NUM / 4) {
                float4 v = ann4[tid], c = cln4[tid];
                v.x = fmaf(v.x, invn, c.x);
                v.y = fmaf(v.y, invn, c.y);
                v.z = fmaf(v.z, invn, c.z);
                v.w = fmaf(v.w, invn, c.w);
                ann4[tid] = v;
            }
        }

        asm volatile("cp.async.wait_group 0;" ::: "memory");
        __syncthreads();   // #4: normalize + XT[nb] visible locally
    }

    // ---- objf on rank 0: stage sums, write BOTH at tid 0 (valid lzd/lzn) ----
    if (rank == 0) {
        const int fb = len & 1;
        float fd = 0.0f, fn = 0.0f;
        for (int s = tid; s < S_DEN; s += 1024) fd += AD[fb * S_DEN + s] * __ldg(dfinal + s);
        for (int s = tid; s < S_NUM; s += 1024) fn += AN[fb * S_NUM + s] * __ldg(nfinal + b * S_NUM + s);
        #pragma unroll
        for (int o = 16; o; o >>= 1) {
            fd += __shfl_xor_sync(0xffffffffu, fd, o);
            fn += __shfl_xor_sync(0xffffffffu, fn, o);
        }
        if (lane == 0) { SRD[wid] = fd; SRN[wid] = fn; }
        __syncthreads();
        if (tid < 32) {
            float v = SRD[tid];
            #pragma unroll
            for (int o = 16; o; o >>= 1) v += __shfl_xor_sync(0xffffffffu, v, o);
            if (tid == 0) SRD[0] = v;
        } else if (tid < 64) {
            float v = SRN[lane];
            #pragma unroll
            for (int o = 16; o; o >>= 1) v += __shfl_xor_sync(0xffffffffu, v, o);
            if (lane == 0) SRN[0] = v;
        }
        __syncthreads();
        if (tid == 0) {
            g_objd[b] = lzd + logf(SRD[0]);
            g_objn[b] = lzn + logf(SRN[0]);
        }
    }
}

__global__ void k_final(const int* __restrict__ xlen, float* __restrict__ out) {
    int tid = threadIdx.x;  // 32 threads
    float d = g_objd[tid];
    float n = g_objn[tid];
    float l = (float)xlen[tid];
    #pragma unroll
    for (int o = 16; o; o >>= 1) {
        d += __shfl_xor_sync(0xffffffffu, d, o);
        n += __shfl_xor_sync(0xffffffffu, n, o);
        l += __shfl_xor_sync(0xffffffffu, l, o);
    }
    if (tid == 0) out[0] = -(n - d) / l;
}

// ---------------- launch ----------------
extern "C" void kernel_launch(void* const* d_in, const int* in_sizes, int n_in,
                              void* d_out, int out_size) {
    const float* x = (const float*)d_in[0];
    const int* xlen = (const int*)d_in[1];
    const int* de_in = (const int*)d_in[2];
    const int* de_out = (const int*)d_in[3];
    const int* de_pdf = (const int*)d_in[4];
    const float* de_prob = (const float*)d_in[5];
    const float* dleaky = (const float*)d_in[6];
    const float* dfinal = (const float*)d_in[7];
    const int* ne_in = (const int*)d_in[8];
    const int* ne_out = (const int*)d_in[9];
    const int* ne_pdf = (const int*)d_in[10];
    const float* ne_prob = (const float*)d_in[11];
    const float* nleaky = (const float*)d_in[12];
    const float* nfinal = (const float*)d_in[13];
    float* out = (float*)d_out;

    cudaFuncSetAttribute(k_main, cudaFuncAttributeMaxDynamicSharedMemorySize, SMEM_MAIN);

    k_exp<<<(NB * NT * ND / 4 + 1023) / 1024, 1024>>>(x);                 // launch 0
    k_graph<<<NB + 1, 1024>>>(de_out, ne_out);                            // launch 1
    k_scatter<<<256, 256>>>(de_in, de_out, de_pdf, de_prob,
                            ne_in, ne_out, ne_pdf, ne_prob);              // launch 2
    k_main<<<NB * CS, 1024, SMEM_MAIN>>>(xlen, dleaky, dfinal, nleaky, nfinal); // launch 3 (ncu)
    k_final<<<1, 32>>>(xlen, out);                                        // launch 4
}

// round 16
// speedup vs baseline: 2.2909x; 1.0560x over previous
#include <cuda_runtime.h>
#include <cstdint>

#define NB 32
#define NT 400
#define ND 2048
#define S_DEN 2000
#define E_DEN 60000
#define S_NUM 512
#define E_NUM 2048
#define CS 4          // cluster size
#define DPER 15       // den edges per thread (~15000/1024 -> 15)

// ---- dynamic smem layout (bytes) ----
#define OFF_AD    0        // float[2][S_DEN]        16000 (16B aligned)
#define OFF_CLD   16000    // float[S_DEN]            8000 (16B aligned)
#define OFF_XT    24000    // float[2][ND]           16384 (16B aligned)
#define OFF_AN    40384    // float[2][S_NUM]         4096 (16B aligned)
#define OFF_CLN   44480    // float[S_NUM]            2048 (16B aligned)
#define OFF_AW    46528    // float[S_DEN]            8000 (16B aligned)
#define OFF_AWN   54528    // float[S_NUM]            2048 (16B aligned)
#define OFF_NE    56576    // uint2[1024]             8192
#define OFF_ND    64768    // u16[1024]               2048
#define OFF_SRD   66816    // float[32]                128
#define OFF_SRN   66944    // float[32]                128
#define OFF_MAILD 67072    // float[2][CS]              32
#define OFF_MAILN 67104    // float[2][CS]              32
#define OFF_DPR   67136    // float[DPER*1024]       61440
#define OFF_DDS   128576   // u16[DPER*1024]         30720
#define SMEM_MAIN 159296

// ---------------- device scratch ----------------
__device__ int g_dfill[S_DEN];
__device__ int g_drow[S_DEN + 1];
__device__ uint2 g_dedge[E_DEN];
__device__ unsigned short g_dout[E_DEN];
__device__ int g_dscut[CS + 1];
__device__ int g_decut[CS + 1];

__device__ int g_nfill[NB * S_NUM];
__device__ int g_nrow[NB * (S_NUM + 1)];
__device__ uint2 g_nedge[NB * E_NUM];
__device__ unsigned short g_nout[NB * E_NUM];
__device__ int g_nscut[NB * (CS + 1)];
__device__ int g_necut[NB * (CS + 1)];

__device__ float g_objd[NB];
__device__ float g_objn[NB];

__device__ float g_xexp[(size_t)NB * NT * ND];

// ---------------- cluster / async primitives ----------------
__device__ __forceinline__ unsigned cluster_rank() {
    unsigned r;
    asm("mov.u32 %0, %%cluster_ctarank;" : "=r"(r));
    return r;
}
__device__ __forceinline__ void cluster_sync() {
    asm volatile("barrier.cluster.arrive.aligned;" ::: "memory");
    asm volatile("barrier.cluster.wait.aligned;" ::: "memory");
}
__device__ __forceinline__ unsigned mapa_addr(const void* p, int rank) {
    unsigned local = (unsigned)__cvta_generic_to_shared(p);
    unsigned remote;
    asm("mapa.shared::cluster.u32 %0, %1, %2;" : "=r"(remote) : "r"(local), "r"(rank));
    return remote;
}
__device__ __forceinline__ void stc_f32(unsigned addr, float v) {
    asm volatile("st.shared::cluster.f32 [%0], %1;" :: "r"(addr), "f"(v) : "memory");
}
__device__ __forceinline__ void stc_f32x4(unsigned addr, float4 v) {
    asm volatile("st.shared::cluster.v4.f32 [%0], {%1, %2, %3, %4};"
                 :: "r"(addr), "f"(v.x), "f"(v.y), "f"(v.z), "f"(v.w) : "memory");
}
__device__ __forceinline__ void cpa16(void* dst, const void* src) {
    unsigned d = (unsigned)__cvta_generic_to_shared(dst);
    asm volatile("cp.async.cg.shared.global [%0], [%1], 16;" :: "r"(d), "l"(src));
}

// ---------------- preprocessing ----------------
__global__ void k_exp(const float* __restrict__ x) {
    size_t i = (size_t)blockIdx.x * blockDim.x + threadIdx.x;
    float4 v = __ldg(((const float4*)x) + i);
    float4 o;
    o.x = __expf(fminf(fmaxf(v.x, -30.f), 30.f));
    o.y = __expf(fminf(fmaxf(v.y, -30.f), 30.f));
    o.z = __expf(fminf(fmaxf(v.z, -30.f), 30.f));
    o.w = __expf(fminf(fmaxf(v.w, -30.f), 30.f));
    ((float4*)g_xexp)[i] = o;
}

// block 0: den zero+hist+scan+cuts (4-state aligned) ; blocks 1..32: num per-b
__global__ void __launch_bounds__(1024) k_graph(const int* __restrict__ de_out,
                                                const int* __restrict__ ne_out) {
    __shared__ int cnt[S_DEN];
    __shared__ int pfx[1024];
    int tid = threadIdx.x;
    if (blockIdx.x == 0) {
        for (int s = tid; s < S_DEN; s += 1024) { cnt[s] = 0; g_dfill[s] = 0; }
        __syncthreads();
        for (int j = tid; j < E_DEN; j += 1024) atomicAdd(&cnt[__ldg(de_out + j)], 1);
        __syncthreads();
        int i0 = 2 * tid, i1 = 2 * tid + 1;
        int c0 = (i0 < S_DEN) ? cnt[i0] : 0;
        int c1 = (i1 < S_DEN) ? cnt[i1] : 0;
        int part = c0 + c1;
        pfx[tid] = part;
        __syncthreads();
        for (int off = 1; off < 1024; off <<= 1) {
            int v = pfx[tid];
            if (tid >= off) v += pfx[tid - off];
            __syncthreads();
            pfx[tid] = v;
            __syncthreads();
        }
        int base = pfx[tid] - part;
        if (i0 <= S_DEN) g_drow[i0] = base;
        if (i1 <= S_DEN) g_drow[i1] = base + c0;
        if (tid == 0) g_drow[S_DEN] = E_DEN;
        __syncthreads();
        for (int s = tid; s < S_DEN; s += 1024) {
            int r = g_drow[s];
            int rp = (s == 0) ? -1 : g_drow[s - 1];
            #pragma unroll
            for (int k = 1; k < CS; k++) {
                int target = k * (E_DEN / CS);
                if (r >= target && rp < target) {
                    int sa = s & ~3;           // 4-state aligned for vec4 broadcast
                    g_dscut[k] = sa;
                    g_decut[k] = g_drow[sa];
                }
            }
        }
        if (tid == 0) { g_dscut[0] = 0; g_decut[0] = 0; g_dscut[CS] = S_DEN; g_decut[CS] = E_DEN; }
    } else {
        int b = blockIdx.x - 1;
        if (tid < S_NUM) { cnt[tid] = 0; g_nfill[b * S_NUM + tid] = 0; }
        __syncthreads();
        for (int j = tid; j < E_NUM; j += 1024)
            atomicAdd(&cnt[__ldg(ne_out + (size_t)b * E_NUM + j)], 1);
        __syncthreads();
        if (tid < S_NUM) pfx[tid] = cnt[tid];
        __syncthreads();
        for (int off = 1; off < S_NUM; off <<= 1) {
            int v = 0;
            if (tid < S_NUM) { v = pfx[tid]; if (tid >= off) v += pfx[tid - off]; }
            __syncthreads();
            if (tid < S_NUM) pfx[tid] = v;
            __syncthreads();
        }
        if (tid < S_NUM) {
            int excl = pfx[tid] - cnt[tid];
            g_nrow[b * (S_NUM + 1) + tid] = excl;
            if (tid == S_NUM - 1) g_nrow[b * (S_NUM + 1) + S_NUM] = E_NUM;
        }
        __syncthreads();
        if (tid < S_NUM) {
            int excl = g_nrow[b * (S_NUM + 1) + tid];
            int exclp = (tid == 0) ? -1 : g_nrow[b * (S_NUM + 1) + tid - 1];
            #pragma unroll
            for (int k = 1; k < CS; k++) {
                int target = k * (E_NUM / CS);
                if (excl >= target && exclp < target) {
                    int sa = tid & ~3;
                    g_nscut[b * (CS + 1) + k] = sa;
                    g_necut[b * (CS + 1) + k] = g_nrow[b * (S_NUM + 1) + sa];
                }
            }
            if (tid == 0) {
                g_nscut[b * (CS + 1)] = 0; g_necut[b * (CS + 1)] = 0;
                g_nscut[b * (CS + 1) + CS] = S_NUM; g_necut[b * (CS + 1) + CS] = E_NUM;
            }
        }
    }
}

__global__ void k_scatter(const int* __restrict__ de_in, const int* __restrict__ de_out,
                          const int* __restrict__ de_pdf, const float* __restrict__ de_prob,
                          const int* __restrict__ ne_in, const int* __restrict__ ne_out,
                          const int* __restrict__ ne_pdf, const float* __restrict__ ne_prob) {
    int i = blockIdx.x * blockDim.x + threadIdx.x;
    if (i < E_DEN) {
        int out = de_out[i];
        int p = atomicAdd(&g_dfill[out], 1);
        int pos = g_drow[out] + p;
        unsigned flag = (pos + 1 == g_drow[out + 1]) ? 1u : 0u;
        unsigned pack = (unsigned)de_in[i] | ((unsigned)de_pdf[i] << 11) | (flag << 22);
        g_dedge[pos] = make_uint2(pack, __float_as_uint(de_prob[i]));
        g_dout[pos] = (unsigned short)out;
    }
    if (i < NB * E_NUM) {
        int b = i >> 11;
        int out = ne_out[i];
        int p = atomicAdd(&g_nfill[b * S_NUM + out], 1);
        int pos = g_nrow[b * (S_NUM + 1) + out] + p;
        unsigned flag = (pos + 1 == g_nrow[b * (S_NUM + 1) + out + 1]) ? 1u : 0u;
        unsigned pack = (unsigned)ne_in[i] | ((unsigned)ne_pdf[i] << 11) | (flag << 22);
        g_nedge[b * E_NUM + pos] = make_uint2(pack, __float_as_uint(ne_prob[i]));
        g_nout[b * E_NUM + pos] = (unsigned short)out;
    }
}

// ---------------- main recursion: 1 cluster (4 CTAs) per utterance ----------------
__global__ void __cluster_dims__(CS, 1, 1) __launch_bounds__(1024, 1)
k_main(const int* __restrict__ xlen,
       const float* __restrict__ dleaky, const float* __restrict__ dfinal,
       const float* __restrict__ nleaky, const float* __restrict__ nfinal) {
    extern __shared__ char sm[];
    float* AD   = (float*)(sm + OFF_AD);      // [2][S_DEN]
    float* CLD  = (float*)(sm + OFF_CLD);
    float* XT   = (float*)(sm + OFF_XT);      // [2][ND]
    float* AN   = (float*)(sm + OFF_AN);      // [2][S_NUM]
    float* CLN  = (float*)(sm + OFF_CLN);
    float* AW   = (float*)(sm + OFF_AW);
    float* AWN  = (float*)(sm + OFF_AWN);
    uint2* NE   = (uint2*)(sm + OFF_NE);
    unsigned short* NDST = (unsigned short*)(sm + OFF_ND);
    float* SRD  = (float*)(sm + OFF_SRD);
    float* SRN  = (float*)(sm + OFF_SRN);
    float* MAILD = (float*)(sm + OFF_MAILD);  // [2][CS]
    float* MAILN = (float*)(sm + OFF_MAILN);  // [2][CS]
    float* DPR  = (float*)(sm + OFF_DPR);     // [DPER*1024]
    unsigned short* DDS = (unsigned short*)(sm + OFF_DDS);

    const int rank = (int)cluster_rank();
    const int b = (int)(blockIdx.x >> 2);
    const int tid = threadIdx.x;
    const int lane = tid & 31, wid = tid >> 5;

    // ---- den slice (shared graph) ----
    const int de0 = g_decut[rank], de1 = g_decut[rank + 1];
    const int ds0 = g_dscut[rank], ds1 = g_dscut[rank + 1];
    const int dn = de1 - de0;
    const unsigned short dl = __ldg(&g_dout[de1 - 1]);
    unsigned epack[DPER];
    #pragma unroll
    for (int k = 0; k < DPER; k++) {
        int j = tid * DPER + k;
        if (j < dn) {
            uint2 w = __ldg(&g_dedge[de0 + j]);
            epack[k] = w.x;
            DPR[k * 1024 + tid] = __uint_as_float(w.y);
            DDS[k * 1024 + tid] = __ldg(&g_dout[de0 + j]);
        } else {
            epack[k] = 0u;
            DPR[k * 1024 + tid] = 0.0f;
            DDS[k * 1024 + tid] = dl;
        }
    }
    for (int s = tid; s < S_DEN; s += 1024) {
        float cl = 1e-5f * __ldg(dleaky + s);
        CLD[s] = cl;
        AD[s] = cl + (s == 0 ? 1.0f : 0.0f);
        AW[s] = 0.0f;
    }
    if (tid < S_NUM) {
        float cl = 1e-20f * __ldg(nleaky + b * S_NUM + tid);
        CLN[tid] = cl;
        AN[tid] = cl + (tid == 0 ? 1.0f : 0.0f);
        AWN[tid] = 0.0f;
    }
    // ---- num slice ----
    const int ne0 = g_necut[b * (CS + 1) + rank], ne1 = g_necut[b * (CS + 1) + rank + 1];
    const int ns0 = g_nscut[b * (CS + 1) + rank], ns1 = g_nscut[b * (CS + 1) + rank + 1];
    const int nn = ne1 - ne0;            // <= ~540, one edge per thread
    if (tid < nn) {
        NE[tid] = __ldg(&g_nedge[(size_t)b * E_NUM + ne0 + tid]);
        NDST[tid] = __ldg(&g_nout[(size_t)b * E_NUM + ne0 + tid]);
    }

    // remote addresses (registers, loop-invariant)
    unsigned adr[CS], anr[CS], mdr[CS], mnr[CS];
    #pragma unroll
    for (int k = 0; k < CS; k++) {
        adr[k] = mapa_addr(AD, k);
        anr[k] = mapa_addr(AN, k);
        mdr[k] = mapa_addr(MAILD, k);
        mnr[k] = mapa_addr(MAILN, k);
    }

    const int len = xlen[b];
    const float* xe = g_xexp + (size_t)b * NT * ND;

    // frame 0 -> XT[0]
    if (tid < 512) cpa16(XT + tid * 4, xe + tid * 4);
    asm volatile("cp.async.commit_group;" ::: "memory");
    asm volatile("cp.async.wait_group 0;" ::: "memory");
    __syncthreads();
    cluster_sync();   // all init visible cluster-wide

    float lzd = 0.0f, lzn = 0.0f;

    for (int t = 0; t < len; ++t) {
        const int buf = t & 1, nb = buf ^ 1;

        if (t + 1 < len && tid < 512)
            cpa16(XT + nb * ND + tid * 4, xe + (size_t)(t + 1) * ND + tid * 4);
        asm volatile("cp.async.commit_group;" ::: "memory");

        const float* ab  = AD + buf * S_DEN;
        const float* xtb = XT + buf * ND;

        // ---- den gather (pack in regs, prob conflict-free LDS) ----
        float ssum = 0.0f;
        {
            float acc = 0.0f;
            #pragma unroll
            for (int k = 0; k < DPER; k++) {
                const unsigned w = epack[k];
                float p = DPR[k * 1024 + tid];
                float av = ab[w & 2047u];
                float xv = xtb[(w >> 11) & 2047u];
                acc = fmaf(av * xv, p, acc);
                if (w & (1u << 22)) {
                    atomicAdd(&AW[DDS[k * 1024 + tid]], acc);
                    ssum += acc;
                    acc = 0.0f;
                }
            }
            if (acc != 0.0f) { atomicAdd(&AW[DDS[(DPER - 1) * 1024 + tid]], acc); ssum += acc; }
        }
        // ---- num gather (1 edge/thread) ----
        float nsum = 0.0f;
        if (tid < nn) {
            uint2 w = NE[tid];
            float av = AN[buf * S_NUM + (w.x & 2047u)];
            float xv = xtb[(w.x >> 11) & 2047u];
            float nacc = av * xv * __uint_as_float(w.y);
            atomicAdd(&AWN[NDST[tid]], nacc);
            nsum = nacc;
        }

        // ---- two-level reduction ----
        #pragma unroll
        for (int o = 16; o; o >>= 1) {
            ssum += __shfl_xor_sync(0xffffffffu, ssum, o);
            nsum += __shfl_xor_sync(0xffffffffu, nsum, o);
        }
        if (lane == 0) { SRD[wid] = ssum; SRN[wid] = nsum; }
        __syncthreads();   // #1: AW/AWN/SRD/SRN complete

        if (tid < 32) {
            float v = SRD[tid];
            #pragma unroll
            for (int o = 16; o; o >>= 1) v += __shfl_xor_sync(0xffffffffu, v, o);
            if (tid == 0) {
                MAILD[buf * CS + rank] = v;
                unsigned moff = 4u * (unsigned)(buf * CS + rank);
                #pragma unroll
                for (int k = 0; k < CS; k++)
                    if (k != rank) stc_f32(mdr[k] + moff, v);
            }
        } else if (tid < 64) {
            float v = SRN[lane];
            #pragma unroll
            for (int o = 16; o; o >>= 1) v += __shfl_xor_sync(0xffffffffu, v, o);
            if (lane == 0) {
                MAILN[buf * CS + rank] = v;
                unsigned moff = 4u * (unsigned)(buf * CS + rank);
                #pragma unroll
                for (int k = 0; k < CS; k++)
                    if (k != rank) stc_f32(mnr[k] + moff, v);
            }
        }

        // ---- vec4 broadcast of RAW anew slices into alpha[nb] of all ranks ----
        {
            float4* AW4 = (float4*)AW;
            float4* AD4 = (float4*)AD;
            const int q0 = ds0 >> 2, q1 = ds1 >> 2;
            for (int q = q0 + tid; q < q1; q += 1024) {
                float4 v = AW4[q];
                AW4[q] = make_float4(0.f, 0.f, 0.f, 0.f);
                const int dst = nb * (S_DEN / 4) + q;
                AD4[dst] = v;   // self: local store
                unsigned off = 16u * (unsigned)dst;
                #pragma unroll
                for (int k = 0; k < CS; k++)
                    if (k != rank) stc_f32x4(adr[k] + off, v);
            }
            float4* AWN4 = (float4*)AWN;
            float4* AN4 = (float4*)AN;
            const int p0 = ns0 >> 2, p1 = ns1 >> 2;
            for (int q = p0 + tid; q < p1; q += 1024) {
                float4 v = AWN4[q];
                AWN4[q] = make_float4(0.f, 0.f, 0.f, 0.f);
                const int dst = nb * (S_NUM / 4) + q;
                AN4[dst] = v;
                unsigned off = 16u * (unsigned)dst;
                #pragma unroll
                for (int k = 0; k < CS; k++)
                    if (k != rank) stc_f32x4(anr[k] + off, v);
            }
        }

        // ---- HW cluster barrier: release all stores, acquire all peers' ----
        cluster_sync();

        // ---- asum locally; vec4 normalize local replica ----
        float asd = MAILD[buf * CS + 0] + MAILD[buf * CS + 1] + MAILD[buf * CS + 2] + MAILD[buf * CS + 3];
        float asn = MAILN[buf * CS + 0] + MAILN[buf * CS + 1] + MAILN[buf * CS + 2] + MAILN[buf * CS + 3];
        float invd = 1.0f / asd;
        float invn = 1.0f / asn;
        if (rank == 0 && tid == 0) { lzd += __logf(asd); lzn += __logf(asn); }

        {
            float4* adn4 = (float4*)(AD + nb * S_DEN);
            const float4* cld4 = (const float4*)CLD;
            for (int q = tid; q < S_DEN / 4; q += 1024) {
                float4 v = adn4[q], c = cld4[q];
                v.x = fmaf(v.x, invd, c.x);
                v.y = fmaf(v.y, invd, c.y);
                v.z = fmaf(v.z, invd, c.z);
                v.w = fmaf(v.w, invd, c.w);
                adn4[q] = v;
            }
            float4* ann4 = (float4*)(AN + nb * S_NUM);
            const float4* cln4 = (const float4*)CLN;
            if (tid < S_NUM / 4) {
                float4 v = ann4[tid], c = cln4[tid];
                v.x = fmaf(v.x, invn, c.x);
                v.y = fmaf(v.y, invn, c.y);
                v.z = fmaf(v.z, invn, c.z);
                v.w = fmaf(v.w, invn, c.w);
                ann4[tid] = v;
            }
        }

        asm volatile("cp.async.wait_group 0;" ::: "memory");
        __syncthreads();   // #2: normalize + XT[nb] visible locally
    }

    // ---- objf on rank 0: stage sums, write BOTH at tid 0 (valid lzd/lzn) ----
    if (rank == 0) {
        const int fb = len & 1;
        float fd = 0.0f, fn = 0.0f;
        for (int s = tid; s < S_DEN; s += 1024) fd += AD[fb * S_DEN + s] * __ldg(dfinal + s);
        for (int s = tid; s < S_NUM; s += 1024) fn += AN[fb * S_NUM + s] * __ldg(nfinal + b * S_NUM + s);
        #pragma unroll
        for (int o = 16; o; o >>= 1) {
            fd += __shfl_xor_sync(0xffffffffu, fd, o);
            fn += __shfl_xor_sync(0xffffffffu, fn, o);
        }
        if (lane == 0) { SRD[wid] = fd; SRN[wid] = fn; }
        __syncthreads();
        if (tid < 32) {
            float v = SRD[tid];
            #pragma unroll
            for (int o = 16; o; o >>= 1) v += __shfl_xor_sync(0xffffffffu, v, o);
            if (tid == 0) SRD[0] = v;
        } else if (tid < 64) {
            float v = SRN[lane];
            #pragma unroll
            for (int o = 16; o; o >>= 1) v += __shfl_xor_sync(0xffffffffu, v, o);
            if (lane == 0) SRN[0] = v;
        }
        __syncthreads();
        if (tid == 0) {
            g_objd[b] = lzd + logf(SRD[0]);
            g_objn[b] = lzn + logf(SRN[0]);
        }
    }
}

__global__ void k_final(const int* __restrict__ xlen, float* __restrict__ out) {
    int tid = threadIdx.x;  // 32 threads
    float d = g_objd[tid];
    float n = g_objn[tid];
    float l = (float)xlen[tid];
    #pragma unroll
    for (int o = 16; o; o >>= 1) {
        d += __shfl_xor_sync(0xffffffffu, d, o);
        n += __shfl_xor_sync(0xffffffffu, n, o);
        l += __shfl_xor_sync(0xffffffffu, l, o);
    }
    if (tid == 0) out[0] = -(n - d) / l;
}

// ---------------- launch ----------------
extern "C" void kernel_launch(void* const* d_in, const int* in_sizes, int n_in,
                              void* d_out, int out_size) {
    const float* x = (const float*)d_in[0];
    const int* xlen = (const int*)d_in[1];
    const int* de_in = (const int*)d_in[2];
    const int* de_out = (const int*)d_in[3];
    const int* de_pdf = (const int*)d_in[4];
    const float* de_prob = (const float*)d_in[5];
    const float* dleaky = (const float*)d_in[6];
    const float* dfinal = (const float*)d_in[7];
    const int* ne_in = (const int*)d_in[8];
    const int* ne_out = (const int*)d_in[9];
    const int* ne_pdf = (const int*)d_in[10];
    const float* ne_prob = (const float*)d_in[11];
    const float* nleaky = (const float*)d_in[12];
    const float* nfinal = (const float*)d_in[13];
    float* out = (float*)d_out;

    cudaFuncSetAttribute(k_main, cudaFuncAttributeMaxDynamicSharedMemorySize, SMEM_MAIN);

    k_exp<<<(NB * NT * ND / 4 + 1023) / 1024, 1024>>>(x);                 // launch 0
    k_graph<<<NB + 1, 1024>>>(de_out, ne_out);                            // launch 1
    k_scatter<<<256, 256>>>(de_in, de_out, de_pdf, de_prob,
                            ne_in, ne_out, ne_pdf, ne_prob);              // launch 2
    k_main<<<NB * CS, 1024, SMEM_MAIN>>>(xlen, dleaky, dfinal, nleaky, nfinal); // launch 3 (ncu)
    k_final<<<1, 32>>>(xlen, out);                                        // launch 4
}

// round 17
// speedup vs baseline: 2.3682x; 1.0338x over previous
#include <cuda_runtime.h>
#include <cstdint>

#define NB 32
#define NT 400
#define ND 2048
#define S_DEN 2000
#define E_DEN 60000
#define S_NUM 512
#define E_NUM 2048
#define CS 4          // cluster size
#define NTHR 768      // threads per CTA (768*85 regs = full RF, no spill)
#define DPER 20       // den edges per thread (768*20 = 15360 >= ~15060 max slice)

// ---- dynamic smem layout (bytes) ----
#define OFF_AD    0        // float[2][S_DEN]        16000 (16B aligned)
#define OFF_CLD   16000    // float[S_DEN]            8000 (16B aligned)
#define OFF_XT    24000    // float[2][ND]           16384 (16B aligned)
#define OFF_AN    40384    // float[2][S_NUM]         4096 (16B aligned)
#define OFF_CLN   44480    // float[S_NUM]            2048 (16B aligned)
#define OFF_AW    46528    // float[S_DEN]            8000 (16B aligned)
#define OFF_AWN   54528    // float[S_NUM]            2048 (16B aligned)
#define OFF_NE    56576    // uint2[1024]             8192
#define OFF_ND    64768    // u16[1024]               2048
#define OFF_SRD   66816    // float[32]                128
#define OFF_SRN   66944    // float[32]                128
#define OFF_MAILD 67072    // float[2][CS]              32
#define OFF_MAILN 67104    // float[2][CS]              32
#define OFF_DPR   67136    // float[DPER*NTHR]       61440
#define OFF_DDS   128576   // u16[DPER*NTHR]         30720
#define SMEM_MAIN 159296

// ---------------- device scratch ----------------
__device__ int g_dfill[S_DEN];
__device__ int g_drow[S_DEN + 1];
__device__ uint2 g_dedge[E_DEN];
__device__ unsigned short g_dout[E_DEN];
__device__ int g_dscut[CS + 1];
__device__ int g_decut[CS + 1];

__device__ int g_nfill[NB * S_NUM];
__device__ int g_nrow[NB * (S_NUM + 1)];
__device__ uint2 g_nedge[NB * E_NUM];
__device__ unsigned short g_nout[NB * E_NUM];
__device__ int g_nscut[NB * (CS + 1)];
__device__ int g_necut[NB * (CS + 1)];

__device__ float g_objd[NB];
__device__ float g_objn[NB];

__device__ float g_xexp[(size_t)NB * NT * ND];

// ---------------- cluster / async primitives ----------------
__device__ __forceinline__ unsigned cluster_rank() {
    unsigned r;
    asm("mov.u32 %0, %%cluster_ctarank;" : "=r"(r));
    return r;
}
__device__ __forceinline__ void cluster_sync() {
    asm volatile("barrier.cluster.arrive.aligned;" ::: "memory");
    asm volatile("barrier.cluster.wait.aligned;" ::: "memory");
}
__device__ __forceinline__ unsigned mapa_addr(const void* p, int rank) {
    unsigned local = (unsigned)__cvta_generic_to_shared(p);
    unsigned remote;
    asm("mapa.shared::cluster.u32 %0, %1, %2;" : "=r"(remote) : "r"(local), "r"(rank));
    return remote;
}
__device__ __forceinline__ void stc_f32(unsigned addr, float v) {
    asm volatile("st.shared::cluster.f32 [%0], %1;" :: "r"(addr), "f"(v) : "memory");
}
__device__ __forceinline__ void stc_f32x4(unsigned addr, float4 v) {
    asm volatile("st.shared::cluster.v4.f32 [%0], {%1, %2, %3, %4};"
                 :: "r"(addr), "f"(v.x), "f"(v.y), "f"(v.z), "f"(v.w) : "memory");
}
__device__ __forceinline__ void cpa16(void* dst, const void* src) {
    unsigned d = (unsigned)__cvta_generic_to_shared(dst);
    asm volatile("cp.async.cg.shared.global [%0], [%1], 16;" :: "r"(d), "l"(src));
}

// ---------------- preprocessing ----------------
__global__ void k_exp(const float* __restrict__ x) {
    size_t i = (size_t)blockIdx.x * blockDim.x + threadIdx.x;
    float4 v = __ldg(((const float4*)x) + i);
    float4 o;
    o.x = __expf(fminf(fmaxf(v.x, -30.f), 30.f));
    o.y = __expf(fminf(fmaxf(v.y, -30.f), 30.f));
    o.z = __expf(fminf(fmaxf(v.z, -30.f), 30.f));
    o.w = __expf(fminf(fmaxf(v.w, -30.f), 30.f));
    ((float4*)g_xexp)[i] = o;
}

// block 0: den zero+hist+scan+cuts (4-state aligned) ; blocks 1..32: num per-b
__global__ void __launch_bounds__(1024) k_graph(const int* __restrict__ de_out,
                                                const int* __restrict__ ne_out) {
    __shared__ int cnt[S_DEN];
    __shared__ int pfx[1024];
    int tid = threadIdx.x;
    if (blockIdx.x == 0) {
        for (int s = tid; s < S_DEN; s += 1024) { cnt[s] = 0; g_dfill[s] = 0; }
        __syncthreads();
        for (int j = tid; j < E_DEN; j += 1024) atomicAdd(&cnt[__ldg(de_out + j)], 1);
        __syncthreads();
        int i0 = 2 * tid, i1 = 2 * tid + 1;
        int c0 = (i0 < S_DEN) ? cnt[i0] : 0;
        int c1 = (i1 < S_DEN) ? cnt[i1] : 0;
        int part = c0 + c1;
        pfx[tid] = part;
        __syncthreads();
        for (int off = 1; off < 1024; off <<= 1) {
            int v = pfx[tid];
            if (tid >= off) v += pfx[tid - off];
            __syncthreads();
            pfx[tid] = v;
            __syncthreads();
        }
        int base = pfx[tid] - part;
        if (i0 <= S_DEN) g_drow[i0] = base;
        if (i1 <= S_DEN) g_drow[i1] = base + c0;
        if (tid == 0) g_drow[S_DEN] = E_DEN;
        __syncthreads();
        for (int s = tid; s < S_DEN; s += 1024) {
            int r = g_drow[s];
            int rp = (s == 0) ? -1 : g_drow[s - 1];
            #pragma unroll
            for (int k = 1; k < CS; k++) {
                int target = k * (E_DEN / CS);
                if (r >= target && rp < target) {
                    int sa = s & ~3;           // 4-state aligned for vec4 broadcast
                    g_dscut[k] = sa;
                    g_decut[k] = g_drow[sa];
                }
            }
        }
        if (tid == 0) { g_dscut[0] = 0; g_decut[0] = 0; g_dscut[CS] = S_DEN; g_decut[CS] = E_DEN; }
    } else {
        int b = blockIdx.x - 1;
        if (tid < S_NUM) { cnt[tid] = 0; g_nfill[b * S_NUM + tid] = 0; }
        __syncthreads();
        for (int j = tid; j < E_NUM; j += 1024)
            atomicAdd(&cnt[__ldg(ne_out + (size_t)b * E_NUM + j)], 1);
        __syncthreads();
        if (tid < S_NUM) pfx[tid] = cnt[tid];
        __syncthreads();
        for (int off = 1; off < S_NUM; off <<= 1) {
            int v = 0;
            if (tid < S_NUM) { v = pfx[tid]; if (tid >= off) v += pfx[tid - off]; }
            __syncthreads();
            if (tid < S_NUM) pfx[tid] = v;
            __syncthreads();
        }
        if (tid < S_NUM) {
            int excl = pfx[tid] - cnt[tid];
            g_nrow[b * (S_NUM + 1) + tid] = excl;
            if (tid == S_NUM - 1) g_nrow[b * (S_NUM + 1) + S_NUM] = E_NUM;
        }
        __syncthreads();
        if (tid < S_NUM) {
            int excl = g_nrow[b * (S_NUM + 1) + tid];
            int exclp = (tid == 0) ? -1 : g_nrow[b * (S_NUM + 1) + tid - 1];
            #pragma unroll
            for (int k = 1; k < CS; k++) {
                int target = k * (E_NUM / CS);
                if (excl >= target && exclp < target) {
                    int sa = tid & ~3;
                    g_nscut[b * (CS + 1) + k] = sa;
                    g_necut[b * (CS + 1) + k] = g_nrow[b * (S_NUM + 1) + sa];
                }
            }
            if (tid == 0) {
                g_nscut[b * (CS + 1)] = 0; g_necut[b * (CS + 1)] = 0;
                g_nscut[b * (CS + 1) + CS] = S_NUM; g_necut[b * (CS + 1) + CS] = E_NUM;
            }
        }
    }
}

__global__ void k_scatter(const int* __restrict__ de_in, const int* __restrict__ de_out,
                          const int* __restrict__ de_pdf, const float* __restrict__ de_prob,
                          const int* __restrict__ ne_in, const int* __restrict__ ne_out,
                          const int* __restrict__ ne_pdf, const float* __restrict__ ne_prob) {
    int i = blockIdx.x * blockDim.x + threadIdx.x;
    if (i < E_DEN) {
        int out = de_out[i];
        int p = atomicAdd(&g_dfill[out], 1);
        int pos = g_drow[out] + p;
        unsigned flag = (pos + 1 == g_drow[out + 1]) ? 1u : 0u;
        unsigned pack = (unsigned)de_in[i] | ((unsigned)de_pdf[i] << 11) | (flag << 22);
        g_dedge[pos] = make_uint2(pack, __float_as_uint(de_prob[i]));
        g_dout[pos] = (unsigned short)out;
    }
    if (i < NB * E_NUM) {
        int b = i >> 11;
        int out = ne_out[i];
        int p = atomicAdd(&g_nfill[b * S_NUM + out], 1);
        int pos = g_nrow[b * (S_NUM + 1) + out] + p;
        unsigned flag = (pos + 1 == g_nrow[b * (S_NUM + 1) + out + 1]) ? 1u : 0u;
        unsigned pack = (unsigned)ne_in[i] | ((unsigned)ne_pdf[i] << 11) | (flag << 22);
        g_nedge[b * E_NUM + pos] = make_uint2(pack, __float_as_uint(ne_prob[i]));
        g_nout[b * E_NUM + pos] = (unsigned short)out;
    }
}

// ---------------- main recursion: 1 cluster (4 CTAs) per utterance ----------------
__global__ void __cluster_dims__(CS, 1, 1) __launch_bounds__(NTHR, 1)
k_main(const int* __restrict__ xlen,
       const float* __restrict__ dleaky, const float* __restrict__ dfinal,
       const float* __restrict__ nleaky, const float* __restrict__ nfinal) {
    extern __shared__ char sm[];
    float* AD   = (float*)(sm + OFF_AD);      // [2][S_DEN]
    float* CLD  = (float*)(sm + OFF_CLD);
    float* XT   = (float*)(sm + OFF_XT);      // [2][ND]
    float* AN   = (float*)(sm + OFF_AN);      // [2][S_NUM]
    float* CLN  = (float*)(sm + OFF_CLN);
    float* AW   = (float*)(sm + OFF_AW);
    float* AWN  = (float*)(sm + OFF_AWN);
    uint2* NE   = (uint2*)(sm + OFF_NE);
    unsigned short* NDST = (unsigned short*)(sm + OFF_ND);
    float* SRD  = (float*)(sm + OFF_SRD);
    float* SRN  = (float*)(sm + OFF_SRN);
    float* MAILD = (float*)(sm + OFF_MAILD);  // [2][CS]
    float* MAILN = (float*)(sm + OFF_MAILN);  // [2][CS]
    float* DPR  = (float*)(sm + OFF_DPR);     // [DPER*NTHR]
    unsigned short* DDS = (unsigned short*)(sm + OFF_DDS);

    const int rank = (int)cluster_rank();
    const int b = (int)(blockIdx.x >> 2);
    const int tid = threadIdx.x;
    const int lane = tid & 31, wid = tid >> 5;

    // ---- den slice (shared graph) ----
    const int de0 = g_decut[rank], de1 = g_decut[rank + 1];
    const int ds0 = g_dscut[rank], ds1 = g_dscut[rank + 1];
    const int dn = de1 - de0;
    const unsigned short dl = __ldg(&g_dout[de1 - 1]);
    unsigned epack[DPER];
    #pragma unroll
    for (int k = 0; k < DPER; k++) {
        int j = tid * DPER + k;
        if (j < dn) {
            uint2 w = __ldg(&g_dedge[de0 + j]);
            epack[k] = w.x;
            DPR[k * NTHR + tid] = __uint_as_float(w.y);
            DDS[k * NTHR + tid] = __ldg(&g_dout[de0 + j]);
        } else {
            epack[k] = 0u;
            DPR[k * NTHR + tid] = 0.0f;
            DDS[k * NTHR + tid] = dl;
        }
    }
    for (int s = tid; s < S_DEN; s += NTHR) {
        float cl = 1e-5f * __ldg(dleaky + s);
        CLD[s] = cl;
        AD[s] = cl + (s == 0 ? 1.0f : 0.0f);
        AW[s] = 0.0f;
    }
    if (tid < S_NUM) {
        float cl = 1e-20f * __ldg(nleaky + b * S_NUM + tid);
        CLN[tid] = cl;
        AN[tid] = cl + (tid == 0 ? 1.0f : 0.0f);
        AWN[tid] = 0.0f;
    }
    if (tid < 32) { SRD[tid] = 0.0f; SRN[tid] = 0.0f; }  // pad entries 24..31 stay 0
    // ---- num slice ----
    const int ne0 = g_necut[b * (CS + 1) + rank], ne1 = g_necut[b * (CS + 1) + rank + 1];
    const int ns0 = g_nscut[b * (CS + 1) + rank], ns1 = g_nscut[b * (CS + 1) + rank + 1];
    const int nn = ne1 - ne0;            // <= ~540, one edge per thread
    if (tid < nn) {
        NE[tid] = __ldg(&g_nedge[(size_t)b * E_NUM + ne0 + tid]);
        NDST[tid] = __ldg(&g_nout[(size_t)b * E_NUM + ne0 + tid]);
    }

    // remote addresses (registers, loop-invariant)
    unsigned adr[CS], anr[CS], mdr[CS], mnr[CS];
    #pragma unroll
    for (int k = 0; k < CS; k++) {
        adr[k] = mapa_addr(AD, k);
        anr[k] = mapa_addr(AN, k);
        mdr[k] = mapa_addr(MAILD, k);
        mnr[k] = mapa_addr(MAILN, k);
    }

    const int len = xlen[b];
    const float* xe = g_xexp + (size_t)b * NT * ND;

    // frame 0 -> XT[0]
    if (tid < 512) cpa16(XT + tid * 4, xe + tid * 4);
    asm volatile("cp.async.commit_group;" ::: "memory");
    asm volatile("cp.async.wait_group 0;" ::: "memory");
    __syncthreads();
    cluster_sync();   // all init visible cluster-wide

    float lzd = 0.0f, lzn = 0.0f;

    for (int t = 0; t < len; ++t) {
        const int buf = t & 1, nb = buf ^ 1;

        if (t + 1 < len && tid < 512)
            cpa16(XT + nb * ND + tid * 4, xe + (size_t)(t + 1) * ND + tid * 4);
        asm volatile("cp.async.commit_group;" ::: "memory");

        const float* ab  = AD + buf * S_DEN;
        const float* xtb = XT + buf * ND;

        // ---- den gather (pack in regs, prob conflict-free LDS) ----
        float ssum = 0.0f;
        {
            float acc = 0.0f;
            #pragma unroll
            for (int k = 0; k < DPER; k++) {
                const unsigned w = epack[k];
                float p = DPR[k * NTHR + tid];
                float av = ab[w & 2047u];
                float xv = xtb[(w >> 11) & 2047u];
                acc = fmaf(av * xv, p, acc);
                if (w & (1u << 22)) {
                    atomicAdd(&AW[DDS[k * NTHR + tid]], acc);
                    ssum += acc;
                    acc = 0.0f;
                }
            }
            if (acc != 0.0f) { atomicAdd(&AW[DDS[(DPER - 1) * NTHR + tid]], acc); ssum += acc; }
        }
        // ---- num gather (1 edge/thread) ----
        float nsum = 0.0f;
        if (tid < nn) {
            uint2 w = NE[tid];
            float av = AN[buf * S_NUM + (w.x & 2047u)];
            float xv = xtb[(w.x >> 11) & 2047u];
            float nacc = av * xv * __uint_as_float(w.y);
            atomicAdd(&AWN[NDST[tid]], nacc);
            nsum = nacc;
        }

        // ---- two-level reduction (24 warps; SRD/SRN padded to 32 with zeros) ----
        #pragma unroll
        for (int o = 16; o; o >>= 1) {
            ssum += __shfl_xor_sync(0xffffffffu, ssum, o);
            nsum += __shfl_xor_sync(0xffffffffu, nsum, o);
        }
        if (lane == 0) { SRD[wid] = ssum; SRN[wid] = nsum; }
        __syncthreads();   // #1: AW/AWN/SRD/SRN complete

        if (tid < 32) {
            float v = SRD[tid];
            #pragma unroll
            for (int o = 16; o; o >>= 1) v += __shfl_xor_sync(0xffffffffu, v, o);
            if (tid == 0) {
                MAILD[buf * CS + rank] = v;
                unsigned moff = 4u * (unsigned)(buf * CS + rank);
                #pragma unroll
                for (int k = 0; k < CS; k++)
                    if (k != rank) stc_f32(mdr[k] + moff, v);
            }
        } else if (tid < 64) {
            float v = SRN[lane];
            #pragma unroll
            for (int o = 16; o; o >>= 1) v += __shfl_xor_sync(0xffffffffu, v, o);
            if (lane == 0) {
                MAILN[buf * CS + rank] = v;
                unsigned moff = 4u * (unsigned)(buf * CS + rank);
                #pragma unroll
                for (int k = 0; k < CS; k++)
                    if (k != rank) stc_f32(mnr[k] + moff, v);
            }
        }

        // ---- vec4 broadcast of RAW anew slices into alpha[nb] of all ranks ----
        {
            float4* AW4 = (float4*)AW;
            float4* AD4 = (float4*)AD;
            const int q0 = ds0 >> 2, q1 = ds1 >> 2;
            for (int q = q0 + tid; q < q1; q += NTHR) {
                float4 v = AW4[q];
                AW4[q] = make_float4(0.f, 0.f, 0.f, 0.f);
                const int dst = nb * (S_DEN / 4) + q;
                AD4[dst] = v;   // self: local store
                unsigned off = 16u * (unsigned)dst;
                #pragma unroll
                for (int k = 0; k < CS; k++)
                    if (k != rank) stc_f32x4(adr[k] + off, v);
            }
            float4* AWN4 = (float4*)AWN;
            float4* AN4 = (float4*)AN;
            const int p0 = ns0 >> 2, p1 = ns1 >> 2;
            for (int q = p0 + tid; q < p1; q += NTHR) {
                float4 v = AWN4[q];
                AWN4[q] = make_float4(0.f, 0.f, 0.f, 0.f);
                const int dst = nb * (S_NUM / 4) + q;
                AN4[dst] = v;
                unsigned off = 16u * (unsigned)dst;
                #pragma unroll
                for (int k = 0; k < CS; k++)
                    if (k != rank) stc_f32x4(anr[k] + off, v);
            }
        }

        // ---- HW cluster barrier: release all stores, acquire all peers' ----
        cluster_sync();

        // ---- asum locally; vec4 normalize local replica ----
        float asd = MAILD[buf * CS + 0] + MAILD[buf * CS + 1] + MAILD[buf * CS + 2] + MAILD[buf * CS + 3];
        float asn = MAILN[buf * CS + 0] + MAILN[buf * CS + 1] + MAILN[buf * CS + 2] + MAILN[buf * CS + 3];
        float invd = 1.0f / asd;
        float invn = 1.0f / asn;
        if (rank == 0 && tid == 0) { lzd += __logf(asd); lzn += __logf(asn); }

        {
            float4* adn4 = (float4*)(AD + nb * S_DEN);
            const float4* cld4 = (const float4*)CLD;
            for (int q = tid; q < S_DEN / 4; q += NTHR) {
                float4 v = adn4[q], c = cld4[q];
                v.x = fmaf(v.x, invd, c.x);
                v.y = fmaf(v.y, invd, c.y);
                v.z = fmaf(v.z, invd, c.z);
                v.w = fmaf(v.w, invd, c.w);
                adn4[q] = v;
            }
            float4* ann4 = (float4*)(AN + nb * S_NUM);
            const float4* cln4 = (const float4*)CLN;
            if (tid < S_NUM / 4) {
                float4 v = ann4[tid], c = cln4[tid];
                v.x = fmaf(v.x, invn, c.x);
                v.y = fmaf(v.y, invn, c.y);
                v.z = fmaf(v.z, invn, c.z);
                v.w = fmaf(v.w, invn, c.w);
                ann4[tid] = v;
            }
        }

        asm volatile("cp.async.wait_group 0;" ::: "memory");
        __syncthreads();   // #2: normalize + XT[nb] visible locally
    }

    // ---- objf on rank 0: stage sums, write BOTH at tid 0 (valid lzd/lzn) ----
    if (rank == 0) {
        const int fb = len & 1;
        float fd = 0.0f, fn = 0.0f;
        for (int s = tid; s < S_DEN; s += NTHR) fd += AD[fb * S_DEN + s] * __ldg(dfinal + s);
        for (int s = tid; s < S_NUM; s += NTHR) fn += AN[fb * S_NUM + s] * __ldg(nfinal + b * S_NUM + s);
        #pragma unroll
        for (int o = 16; o; o >>= 1) {
            fd += __shfl_xor_sync(0xffffffffu, fd, o);
            fn += __shfl_xor_sync(0xffffffffu, fn, o);
        }
        if (lane == 0) { SRD[wid] = fd; SRN[wid] = fn; }
        __syncthreads();
        if (tid < 32) {
            float v = SRD[tid];       // entries 24..31 are 0 (padded at init)
            #pragma unroll
            for (int o = 16; o; o >>= 1) v += __shfl_xor_sync(0xffffffffu, v, o);
            if (tid == 0) SRD[0] = v;
        } else if (tid < 64) {
            float v = SRN[lane];
            #pragma unroll
            for (int o = 16; o; o >>= 1) v += __shfl_xor_sync(0xffffffffu, v, o);
            if (lane == 0) SRN[0] = v;
        }
        __syncthreads();
        if (tid == 0) {
            g_objd[b] = lzd + logf(SRD[0]);
            g_objn[b] = lzn + logf(SRN[0]);
        }
    }
}

__global__ void k_final(const int* __restrict__ xlen, float* __restrict__ out) {
    int tid = threadIdx.x;  // 32 threads
    float d = g_objd[tid];
    float n = g_objn[tid];
    float l = (float)xlen[tid];
    #pragma unroll
    for (int o = 16; o; o >>= 1) {
        d += __shfl_xor_sync(0xffffffffu, d, o);
        n += __shfl_xor_sync(0xffffffffu, n, o);
        l += __shfl_xor_sync(0xffffffffu, l, o);
    }
    if (tid == 0) out[0] = -(n - d) / l;
}

// ---------------- launch ----------------
extern "C" void kernel_launch(void* const* d_in, const int* in_sizes, int n_in,
                              void* d_out, int out_size) {
    const float* x = (const float*)d_in[0];
    const int* xlen = (const int*)d_in[1];
    const int* de_in = (const int*)d_in[2];
    const int* de_out = (const int*)d_in[3];
    const int* de_pdf = (const int*)d_in[4];
    const float* de_prob = (const float*)d_in[5];
    const float* dleaky = (const float*)d_in[6];
    const float* dfinal = (const float*)d_in[7];
    const int* ne_in = (const int*)d_in[8];
    const int* ne_out = (const int*)d_in[9];
    const int* ne_pdf = (const int*)d_in[10];
    const float* ne_prob = (const float*)d_in[11];
    const float* nleaky = (const float*)d_in[12];
    const float* nfinal = (const float*)d_in[13];
    float* out = (float*)d_out;

    cudaFuncSetAttribute(k_main, cudaFuncAttributeMaxDynamicSharedMemorySize, SMEM_MAIN);

    k_exp<<<(NB * NT * ND / 4 + 1023) / 1024, 1024>>>(x);                 // launch 0
    k_graph<<<NB + 1, 1024>>>(de_out, ne_out);                            // launch 1
    k_scatter<<<256, 256>>>(de_in, de_out, de_pdf, de_prob,
                            ne_in, ne_out, ne_pdf, ne_prob);              // launch 2
    k_main<<<NB * CS, NTHR, SMEM_MAIN>>>(xlen, dleaky, dfinal, nleaky, nfinal); // launch 3 (ncu)
    k_final<<<1, 32>>>(xlen, out);                                        // launch 4
}